// round 1
// baseline (speedup 1.0000x reference)
#include <cuda_runtime.h>
#include <cstdint>

#define N_ROWS 8192
#define D_DIM 1024
#define K_CLS 80
#define KP1 81
#define M_CAND 2048
#define TOPK_N 100
#define IMG_H_F 800.0f
#define IMG_W_F 1216.0f
#define SCORE_T 0.05f
#define NMS_T 0.5f
#define SCALE_CLAMP_F 4.135166556742356f  // log(1000/16)

// ---------------- static device scratch (no allocs allowed) ----------------
__device__ uint64_t      g_keys[N_ROWS * K_CLS];      // 5.24 MB
__device__ unsigned int  g_hist[65536];
__device__ uint64_t      g_binbuf[8192];
__device__ uint64_t      g_selbuf[M_CAND];
__device__ int           g_B, g_countGt, g_needed;
__device__ unsigned int  g_nGt, g_nBin;
__device__ float         g_bboxWt[K_CLS * 4 * D_DIM]; // 1.31 MB, transposed bbox_w
__device__ float         g_candBoxes[M_CAND * 4];
__device__ int           g_selCls[M_CAND];
__device__ int           g_selProp[M_CAND];
__device__ float         g_selScore[M_CAND];
__device__ unsigned char g_selValid[M_CAND];
__device__ uint64_t      g_mask[M_CAND * 32];         // 512 KB

// ---------------- init: zero accumulators each launch ----------------
__global__ void init_kernel() {
    int tid = blockIdx.x * blockDim.x + threadIdx.x;
    int nthr = gridDim.x * blockDim.x;
    for (int i = tid; i < 65536; i += nthr) g_hist[i] = 0;
    for (int i = tid; i < 8192; i += nthr) g_binbuf[i] = 0;
    if (tid == 0) { g_nGt = 0; g_nBin = 0; }
}

// ---------------- transpose bbox_w [1024,320] -> [320,1024] ----------------
__global__ void transpose_kernel(const float* __restrict__ bw) {
    int i = blockIdx.x * blockDim.x + threadIdx.x;   // over 320*1024, k fastest
    if (i < 320 * D_DIM) {
        int c = i / D_DIM, k = i % D_DIM;
        g_bboxWt[i] = bw[k * 320 + c];
    }
}

// ---------------- cls GEMM (8192x1024x81) + softmax + key build ----------------
__global__ __launch_bounds__(256, 2)
void gemm_cls_softmax(const float* __restrict__ x, const float* __restrict__ cw,
                      const float* __restrict__ cb) {
    __shared__ float xs[32][65];        // [k][row], padded
    __shared__ float ws[32][96];        // [k][col], cols padded 81->96 with 0
    __shared__ float logits[64][81];
    __shared__ float red[64][4];
    __shared__ float rmax[64], rsum[64];

    const int t = threadIdx.x;
    const int tx = t & 15, ty = t >> 4;
    const int row0 = blockIdx.x * 64;

    float acc[4][6];
#pragma unroll
    for (int i = 0; i < 4; i++)
#pragma unroll
        for (int j = 0; j < 6; j++) acc[i][j] = 0.f;

    for (int k0 = 0; k0 < D_DIM; k0 += 32) {
        for (int l = t; l < 64 * 32; l += 256) {
            int r = l >> 5, c = l & 31;
            xs[c][r] = x[(size_t)(row0 + r) * D_DIM + k0 + c];
        }
        for (int l = t; l < 32 * 96; l += 256) {
            int kk = l / 96, c = l - kk * 96;
            ws[kk][c] = (c < KP1) ? cw[(size_t)(k0 + kk) * KP1 + c] : 0.f;
        }
        __syncthreads();
#pragma unroll
        for (int kk = 0; kk < 32; kk++) {
            float xv[4], wv[6];
#pragma unroll
            for (int i = 0; i < 4; i++) xv[i] = xs[kk][ty + 16 * i];
#pragma unroll
            for (int j = 0; j < 6; j++) wv[j] = ws[kk][tx + 16 * j];
#pragma unroll
            for (int i = 0; i < 4; i++)
#pragma unroll
                for (int j = 0; j < 6; j++) acc[i][j] += xv[i] * wv[j];
        }
        __syncthreads();
    }
    // store logits + bias
#pragma unroll
    for (int i = 0; i < 4; i++)
#pragma unroll
        for (int j = 0; j < 6; j++) {
            int c = tx + 16 * j;
            if (c < KP1) logits[ty + 16 * i][c] = acc[i][j] + cb[c];
        }
    __syncthreads();

    // softmax: 4 threads per row
    {
        int r = t & 63, p = t >> 6;
        float mx = -1e30f;
        for (int c = p; c < KP1; c += 4) mx = fmaxf(mx, logits[r][c]);
        red[r][p] = mx;
        __syncthreads();
        if (p == 0) rmax[r] = fmaxf(fmaxf(red[r][0], red[r][1]), fmaxf(red[r][2], red[r][3]));
        __syncthreads();
        float s = 0.f;
        float m = rmax[r];
        for (int c = p; c < KP1; c += 4) {
            float e = expf(logits[r][c] - m);
            logits[r][c] = e;
            s += e;
        }
        red[r][p] = s;
        __syncthreads();
        if (p == 0) rsum[r] = red[r][0] + red[r][1] + red[r][2] + red[r][3];
        __syncthreads();
    }
    // build keys for the first 80 cols (drop background), coalesced over c
    for (int l = t; l < 64 * K_CLS; l += 256) {
        int r = l / K_CLS, c = l - r * K_CLS;
        float pr = logits[r][c] / rsum[r];
        unsigned int bits = 0;
        if (pr > SCORE_T) {
            bits = __float_as_uint(pr);
            atomicAdd(&g_hist[bits >> 16], 1u);
        }
        int fid = (row0 + r) * K_CLS + c;
        g_keys[fid] = ((uint64_t)bits << 32) | (uint32_t)(~(uint32_t)fid);
    }
}

// ---------------- pick boundary bin from histogram ----------------
__global__ void pick_kernel() {
    __shared__ unsigned int part[1024];
    int t = threadIdx.x;
    unsigned int s = 0;
    for (int j = 0; j < 64; j++) s += g_hist[t * 64 + j];
    part[t] = s;
    __syncthreads();
    if (t == 0) {
        unsigned int cum = 0;
        int B = 0;
        unsigned int cgt = 0;
        bool found = false;
        for (int c = 1023; c >= 0 && !found; c--) {
            if (cum + part[c] >= (unsigned)M_CAND) {
                for (int bin = c * 64 + 63; bin >= c * 64; bin--) {
                    unsigned int h = g_hist[bin];
                    if (cum + h >= (unsigned)M_CAND) { B = bin; cgt = cum; found = true; break; }
                    cum += h;
                }
            } else {
                cum += part[c];
            }
        }
        if (!found) { B = 0; cgt = cum; }
        g_B = B;
        g_countGt = (int)cgt;
        g_needed = M_CAND - (int)cgt;
    }
}

// ---------------- collect candidates above / at boundary bin ----------------
__global__ void collect_kernel() {
    int i = blockIdx.x * blockDim.x + threadIdx.x;
    if (i >= N_ROWS * K_CLS) return;
    uint64_t k = g_keys[i];
    int hi = (int)(k >> 48);
    int B = g_B;
    if (hi > B) {
        unsigned int p = atomicAdd(&g_nGt, 1u);
        g_selbuf[p] = k;
    } else if (hi == B) {
        // B==0 fallback (fewer than M candidates): only need smallest flat
        // indices among non-candidates; those are guaranteed within fid<8192.
        unsigned int fid = ~(uint32_t)k;
        if (B != 0 || fid < 8192u) {
            unsigned int p = atomicAdd(&g_nBin, 1u);
            if (p < 8192u) g_binbuf[p] = k;
        }
    }
}

// ---------------- bitonic sort helper (descending, in shared) ----------------
__device__ __forceinline__ void bitonic_desc(uint64_t* sm, int n, int t, int nthr) {
    for (unsigned int size = 2; size <= (unsigned)n; size <<= 1) {
        for (unsigned int stride = size >> 1; stride > 0; stride >>= 1) {
            __syncthreads();
            for (unsigned int l = t; l < (unsigned)(n >> 1); l += nthr) {
                unsigned int i = 2u * l - (l & (stride - 1u));
                unsigned int j = i + stride;
                bool desc = (i & size) == 0;
                uint64_t a = sm[i], b = sm[j];
                if (desc ? (a < b) : (a > b)) { sm[i] = b; sm[j] = a; }
            }
        }
    }
    __syncthreads();
}

// ---------------- sort boundary bin, append needed to selbuf ----------------
__global__ void sortbin_kernel() {
    extern __shared__ uint64_t sm8[];
    int t = threadIdx.x;
    for (int i = t; i < 8192; i += 1024) sm8[i] = g_binbuf[i];
    __syncthreads();
    bitonic_desc(sm8, 8192, t, 1024);
    int cgt = g_countGt, need = g_needed;
    for (int i = t; i < need; i += 1024) g_selbuf[cgt + i] = sm8[i];
}

// ---------------- sort the 2048 selected, decode per-slot metadata ----------------
__global__ void sortsel_kernel() {
    __shared__ uint64_t sm[M_CAND];
    int t = threadIdx.x;
    for (int i = t; i < M_CAND; i += 1024) sm[i] = g_selbuf[i];
    __syncthreads();
    bitonic_desc(sm, M_CAND, t, 1024);
    for (int s = t; s < M_CAND; s += 1024) {
        uint64_t k = sm[s];
        unsigned int bits = (unsigned int)(k >> 32);
        int fid = (int)(~(uint32_t)k);
        g_selScore[s] = bits ? __uint_as_float(bits) : -1.0f;
        g_selValid[s] = bits != 0;
        g_selCls[s] = fid % K_CLS;
        g_selProp[s] = fid / K_CLS;
    }
}

// ---------------- per-candidate bbox delta GEMV + decode + clip ----------------
__global__ __launch_bounds__(128)
void decode_kernel(const float* __restrict__ x, const float* __restrict__ bb,
                   const float* __restrict__ proposals) {
    int s = blockIdx.x;
    int cls = g_selCls[s], prop = g_selProp[s];
    int w = threadIdx.x >> 5, lane = threadIdx.x & 31;
    const float* xr = x + (size_t)prop * D_DIM;
    const float* wr = g_bboxWt + (size_t)(cls * 4 + w) * D_DIM;
    float acc = 0.f;
#pragma unroll 8
    for (int k = lane; k < D_DIM; k += 32) acc += xr[k] * wr[k];
#pragma unroll
    for (int o = 16; o; o >>= 1) acc += __shfl_xor_sync(0xffffffffu, acc, o);
    __shared__ float d[4];
    if (lane == 0) d[w] = acc + bb[cls * 4 + w];
    __syncthreads();
    if (threadIdx.x == 0) {
        const float* pb = proposals + (size_t)prop * 4;
        float pw = pb[2] - pb[0], ph = pb[3] - pb[1];
        float cx = pb[0] + 0.5f * pw, cy = pb[1] + 0.5f * ph;
        float dx = d[0] / 10.0f, dy = d[1] / 10.0f;
        float dw = fminf(d[2] / 5.0f, SCALE_CLAMP_F);
        float dh = fminf(d[3] / 5.0f, SCALE_CLAMP_F);
        float pcx = dx * pw + cx, pcy = dy * ph + cy;
        float qw = expf(dw) * pw, qh = expf(dh) * ph;
        float x1 = pcx - 0.5f * qw, y1 = pcy - 0.5f * qh;
        float x2 = pcx + 0.5f * qw, y2 = pcy + 0.5f * qh;
        x1 = fminf(fmaxf(x1, 0.f), IMG_W_F);
        y1 = fminf(fmaxf(y1, 0.f), IMG_H_F);
        x2 = fminf(fmaxf(x2, 0.f), IMG_W_F);
        y2 = fminf(fmaxf(y2, 0.f), IMG_H_F);
        g_candBoxes[s * 4 + 0] = x1;
        g_candBoxes[s * 4 + 1] = y1;
        g_candBoxes[s * 4 + 2] = x2;
        g_candBoxes[s * 4 + 3] = y2;
    }
}

// ---------------- IoU suppression bitmask (class-aware) ----------------
__global__ __launch_bounds__(64)
void iou_kernel() {
    __shared__ float cb[64][4];
    __shared__ int ccls[64];
    int rb = blockIdx.y, cbk = blockIdx.x;
    int t = threadIdx.x;
    int j0 = cbk * 64;
    {
        int j = j0 + t;
        cb[t][0] = g_candBoxes[j * 4 + 0];
        cb[t][1] = g_candBoxes[j * 4 + 1];
        cb[t][2] = g_candBoxes[j * 4 + 2];
        cb[t][3] = g_candBoxes[j * 4 + 3];
        ccls[t] = g_selCls[j];
    }
    __syncthreads();
    int i = rb * 64 + t;
    float bx1 = g_candBoxes[i * 4 + 0], by1 = g_candBoxes[i * 4 + 1];
    float bx2 = g_candBoxes[i * 4 + 2], by2 = g_candBoxes[i * 4 + 3];
    float areaI = (bx2 - bx1) * (by2 - by1);
    int icls = g_selCls[i];
    uint64_t bits = 0;
#pragma unroll 4
    for (int jt = 0; jt < 64; jt++) {
        int jg = j0 + jt;
        if (jg > i && ccls[jt] == icls) {
            float ix1 = fmaxf(bx1, cb[jt][0]);
            float iy1 = fmaxf(by1, cb[jt][1]);
            float ix2 = fminf(bx2, cb[jt][2]);
            float iy2 = fminf(by2, cb[jt][3]);
            float inter = fmaxf(ix2 - ix1, 0.f) * fmaxf(iy2 - iy1, 0.f);
            float areaJ = (cb[jt][2] - cb[jt][0]) * (cb[jt][3] - cb[jt][1]);
            float uni = areaI + areaJ - inter;
            float iou = inter / fmaxf(uni, 1e-9f);
            if (iou > NMS_T) bits |= 1ull << jt;
        }
    }
    g_mask[i * 32 + cbk] = bits;
}

// ---------------- serial NMS scan + final top-100 output ----------------
__global__ __launch_bounds__(256)
void nms_out_kernel(float* __restrict__ out, int out_size) {
    __shared__ unsigned char keep[M_CAND];
    __shared__ short fidx[TOPK_N];

    if (threadIdx.x < 32) {
        int lane = threadIdx.x;
        uint64_t remv = 0;
        for (int i = 0; i < M_CAND; i++) {
            uint64_t m = g_mask[i * 32 + lane];           // prefetchable, independent
            unsigned char v = g_selValid[i];
            uint64_t cur = __shfl_sync(0xffffffffu, remv, i >> 6);
            bool alive = v && !((cur >> (i & 63)) & 1ull);
            if (lane == 0) keep[i] = alive;
            if (alive) remv |= m;
        }
    }
    __syncthreads();
    if (threadIdx.x == 0) {
        int n = 0;
        for (int i = 0; i < M_CAND && n < TOPK_N; i++)
            if (keep[i]) fidx[n++] = (short)i;
        for (int i = 0; i < M_CAND && n < TOPK_N; i++)
            if (!keep[i]) fidx[n++] = (short)i;
    }
    __syncthreads();
    // layout: boxes[100*4], scores[100], cls[100], valid[100] -> 700 floats
    for (int l = threadIdx.x; l < TOPK_N; l += 256) {
        int s = fidx[l];
        bool kp = keep[s] != 0;
        if (4 * l + 3 < out_size) {
            out[4 * l + 0] = g_candBoxes[s * 4 + 0];
            out[4 * l + 1] = g_candBoxes[s * 4 + 1];
            out[4 * l + 2] = g_candBoxes[s * 4 + 2];
            out[4 * l + 3] = g_candBoxes[s * 4 + 3];
        }
        if (400 + l < out_size) out[400 + l] = kp ? g_selScore[s] : -1.0f;
        if (500 + l < out_size) out[500 + l] = (float)g_selCls[s];
        if (600 + l < out_size) out[600 + l] = kp ? 1.0f : 0.0f;
    }
}

// ---------------- launcher ----------------
extern "C" void kernel_launch(void* const* d_in, const int* in_sizes, int n_in,
                              void* d_out, int out_size) {
    const float* x         = (const float*)d_in[0];
    const float* cls_w     = (const float*)d_in[1];
    const float* cls_b     = (const float*)d_in[2];
    const float* bbox_w    = (const float*)d_in[3];
    const float* bbox_b    = (const float*)d_in[4];
    const float* proposals = (const float*)d_in[5];
    float* out = (float*)d_out;

    cudaFuncSetAttribute(sortbin_kernel, cudaFuncAttributeMaxDynamicSharedMemorySize, 65536);

    init_kernel<<<64, 256>>>();
    transpose_kernel<<<(320 * D_DIM + 255) / 256, 256>>>(bbox_w);
    gemm_cls_softmax<<<N_ROWS / 64, 256>>>(x, cls_w, cls_b);
    pick_kernel<<<1, 1024>>>();
    collect_kernel<<<(N_ROWS * K_CLS) / 256, 256>>>();
    sortbin_kernel<<<1, 1024, 65536>>>();
    sortsel_kernel<<<1, 1024>>>();
    decode_kernel<<<M_CAND, 128>>>(x, bbox_b, proposals);
    iou_kernel<<<dim3(32, 32), 64>>>();
    nms_out_kernel<<<1, 256>>>(out, out_size);
}